// round 1
// baseline (speedup 1.0000x reference)
#include <cuda_runtime.h>
#include <cstdint>
#include <math.h>

// Problem constants
#define NROWS   65536          // 64*32*32 flattened vectors
#define DIMD    64
#define KCODES  1024
#define QELEMS  4194304        // 64*64*32*32

// Output layout (float32, outputs concatenated in reference return order):
// [0]                       loss              (1)
// [1 .. 4194304]            quant_out NCHW    (4194304)
// [4194305]                 perplexity        (1)
// [4194306 .. 71303169]     encodings [N,K]   (67108864)
// [71303170 .. 71368705]    idx as float      (65536)
#define O_LOSS  0
#define O_QUANT 1
#define O_PERP  4194305
#define O_ENC   4194306
#define O_IDX   71303170

// ---------------- device scratch (no allocations allowed) ----------------
__device__ float g_embT[DIMD * KCODES];   // emb transposed [d][k]
__device__ float g_B[KCODES];             // ||e_k||^2 (sequential add order)
__device__ int   g_idx[NROWS];
__device__ int   g_hist[KCODES];
__device__ float g_partial[16384];

// ---------------- packed f32x2 helpers (FFMA2 path) ----------------
__device__ __forceinline__ unsigned long long pk2(float lo, float hi) {
    unsigned long long r;
    asm("mov.b64 %0, {%1, %2};" : "=l"(r) : "f"(lo), "f"(hi));
    return r;
}
__device__ __forceinline__ void unpk2(unsigned long long v, float& lo, float& hi) {
    asm("mov.b64 {%0, %1}, %2;" : "=f"(lo), "=f"(hi) : "l"(v));
}
__device__ __forceinline__ unsigned long long ffma2(unsigned long long a,
                                                    unsigned long long b,
                                                    unsigned long long c) {
    unsigned long long d;
    asm("fma.rn.f32x2 %0, %1, %2, %3;" : "=l"(d) : "l"(a), "l"(b), "l"(c));
    return d;
}

// ---------------- prep: transpose emb, codebook norms, zero hist ----------------
__global__ void prep_kernel(const float* __restrict__ emb) {
    int t = threadIdx.x;
    int d = blockIdx.x;               // 64 blocks, 1024 threads
    g_embT[d * KCODES + t] = emb[t * DIMD + d];
    if (blockIdx.x == 0) {
        // B_k = sum_d fl(e*e) with sequential ADD (not FMA) to mirror
        // elementwise-square-then-reduce of the reference.
        const float* er = emb + t * DIMD;
        float s = 0.f;
        for (int dd = 0; dd < DIMD; ++dd) {
            float v = er[dd];
            s = __fadd_rn(s, __fmul_rn(v, v));
        }
        g_B[t] = s;
        g_hist[t] = 0;
    }
}

// ---------------- fused distance GEMM + argmin ----------------
// Block: 128 rows; loops over K in chunks of 64 codes.
// Threads 256 = (tx 0..7 cols) x (ty 0..31 rows); micro-tile 4 rows x 8 cols
// packed into 4x4 f32x2 accumulators.
__global__ void __launch_bounds__(256)
argmin_kernel(const float* __restrict__ inputs, float* __restrict__ out) {
    __shared__ __align__(16) float Xs[DIMD * 128];   // 32 KB  Xs[d][r]
    __shared__ __align__(16) float Es[DIMD * 64];    // 16 KB  Es[d][j]

    const int t  = threadIdx.x;
    const int tx = t & 7;
    const int ty = t >> 3;
    const int tile = blockIdx.x;               // 512 tiles of 128 rows
    const int b   = tile >> 3;                 // batch index (1024 rows per b)
    const int sp0 = (tile & 7) << 7;           // spatial offset within batch
    const float* xbase = inputs + (size_t)b * 65536 + sp0;   // + d*1024 + r

    // Load X tile: Xs[d][r] = inputs[b, d, sp0+r]  (coalesced float4)
    {
        float4* Xs4 = (float4*)Xs;
        #pragma unroll
        for (int i = 0; i < 8; ++i) {
            int id4 = i * 256 + t;             // 2048 float4
            int d = id4 >> 5, rq = id4 & 31;
            Xs4[d * 32 + rq] = *(const float4*)(xbase + d * 1024 + (rq << 2));
        }
    }
    __syncthreads();

    // A_r = sum_d fl(x*x) sequential ADD order (matches reference expression)
    float Ar[4];
    #pragma unroll
    for (int r = 0; r < 4; ++r) {
        float a = 0.f;
        for (int d = 0; d < DIMD; ++d) {
            float v = Xs[d * 128 + (ty << 2) + r];
            a = __fadd_rn(a, __fmul_rn(v, v));
        }
        Ar[r] = a;
    }

    float bestv[4];
    int   besti[4];
    #pragma unroll
    for (int r = 0; r < 4; ++r) { bestv[r] = __int_as_float(0x7f800000); besti[r] = 0; }

    for (int c = 0; c < 16; ++c) {             // 16 chunks of 64 codes
        const int kc = c << 6;
        {   // load E chunk (pre-transposed): Es[d][j] = embT[d][kc+j]
            float4* Es4 = (float4*)Es;
            #pragma unroll
            for (int i = 0; i < 4; ++i) {
                int id4 = i * 256 + t;         // 1024 float4
                int d = id4 >> 4, jq = id4 & 15;
                Es4[d * 16 + jq] = *(const float4*)(g_embT + d * KCODES + kc + (jq << 2));
            }
        }
        __syncthreads();

        unsigned long long acc[4][4];
        #pragma unroll
        for (int r = 0; r < 4; ++r)
            #pragma unroll
            for (int p = 0; p < 4; ++p) acc[r][p] = 0ULL;

        #pragma unroll 4
        for (int d = 0; d < DIMD; ++d) {
            const float4 xa = *(const float4*)(Xs + d * 128 + (ty << 2));
            const float4 ea = *(const float4*)(Es + (d << 6) + (tx << 3));
            const float4 eb = *(const float4*)(Es + (d << 6) + (tx << 3) + 4);
            unsigned long long e0 = pk2(ea.x, ea.y);
            unsigned long long e1 = pk2(ea.z, ea.w);
            unsigned long long e2 = pk2(eb.x, eb.y);
            unsigned long long e3 = pk2(eb.z, eb.w);
            float xr[4] = {xa.x, xa.y, xa.z, xa.w};
            #pragma unroll
            for (int r = 0; r < 4; ++r) {
                unsigned long long xd = pk2(xr[r], xr[r]);
                acc[r][0] = ffma2(xd, e0, acc[r][0]);
                acc[r][1] = ffma2(xd, e1, acc[r][1]);
                acc[r][2] = ffma2(xd, e2, acc[r][2]);
                acc[r][3] = ffma2(xd, e3, acc[r][3]);
            }
        }

        // Epilogue: dist = fl(fl(A+B) - fl(2*dot)), ascending k -> first-min ties
        #pragma unroll
        for (int r = 0; r < 4; ++r) {
            const float A = Ar[r];
            #pragma unroll
            for (int p = 0; p < 4; ++p) {
                float lo, hi;
                unpk2(acc[r][p], lo, hi);
                int j = (tx << 3) + (p << 1);
                float B0 = g_B[kc + j];
                float B1 = g_B[kc + j + 1];
                float d0 = __fsub_rn(__fadd_rn(A, B0), __fmul_rn(2.f, lo));
                float d1 = __fsub_rn(__fadd_rn(A, B1), __fmul_rn(2.f, hi));
                if (d0 < bestv[r]) { bestv[r] = d0; besti[r] = kc + j; }
                if (d1 < bestv[r]) { bestv[r] = d1; besti[r] = kc + j + 1; }
            }
        }
        __syncthreads();   // protect Es before next chunk's load
    }

    // Cross-thread reduction over the 8 col-threads of each row (lane groups of 8)
    #pragma unroll
    for (int r = 0; r < 4; ++r) {
        float v = bestv[r];
        int   k = besti[r];
        #pragma unroll
        for (int off = 4; off > 0; off >>= 1) {
            float v2 = __shfl_down_sync(0xffffffffu, v, off, 8);
            int   k2 = __shfl_down_sync(0xffffffffu, k, off, 8);
            if (v2 < v || (v2 == v && k2 < k)) { v = v2; k = k2; }
        }
        if (tx == 0) {
            int n = (tile << 7) + (ty << 2) + r;
            g_idx[n] = k;
            out[(size_t)O_IDX + n] = (float)k;
            atomicAdd(&g_hist[k], 1);
        }
    }
}

// ---------------- quantized gather (NCHW) + MSE partials ----------------
__global__ void quant_kernel(const float* __restrict__ inputs,
                             const float* __restrict__ emb,
                             float* __restrict__ out) {
    int e  = blockIdx.x * 256 + threadIdx.x;   // element of NCHW tensor
    int sp = e & 1023;
    int d  = (e >> 10) & 63;
    int b  = e >> 16;
    int n  = (b << 10) + sp;
    int id = g_idx[n];
    float q = emb[id * DIMD + d];
    float x = inputs[e];
    out[O_QUANT + e] = q;                      // straight-through forward value
    float df = q - x;
    float s  = df * df;
    #pragma unroll
    for (int off = 16; off > 0; off >>= 1)
        s += __shfl_down_sync(0xffffffffu, s, off);
    __shared__ float ws[8];
    if ((threadIdx.x & 31) == 0) ws[threadIdx.x >> 5] = s;
    __syncthreads();
    if (threadIdx.x == 0) {
        float tot = 0.f;
        #pragma unroll
        for (int i = 0; i < 8; ++i) tot += ws[i];
        g_partial[blockIdx.x] = tot;           // deterministic (fixed slots)
    }
}

// ---------------- scalars: loss + perplexity ----------------
__global__ void finalize_kernel(float* __restrict__ out) {
    __shared__ double sh[256];
    int t = threadIdx.x;
    double s = 0.0;
    for (int i = t; i < 16384; i += 256) s += (double)g_partial[i];
    sh[t] = s;
    __syncthreads();
    for (int off = 128; off > 0; off >>= 1) {
        if (t < off) sh[t] += sh[t + off];
        __syncthreads();
    }
    double S = sh[0];
    __syncthreads();
    double h = 0.0;
    for (int k = t; k < KCODES; k += 256) {
        double p = (double)g_hist[k] * (1.0 / 65536.0);
        h += p * log(p + 1e-10);
    }
    sh[t] = h;
    __syncthreads();
    for (int off = 128; off > 0; off >>= 1) {
        if (t < off) sh[t] += sh[t + off];
        __syncthreads();
    }
    if (t == 0) {
        float perp = (float)exp(-sh[0]);
        float mse  = (float)(S * (1.0 / (double)QELEMS));
        // loss = q_latent + 0.25*e_latent + diversity ; q_latent == e_latent == mse
        float loss = __fadd_rn(mse, __fmul_rn(0.25f, mse));
        float dv   = __fdiv_rn(__fmul_rn(0.1f, __fsub_rn(1024.0f, perp)), 1024.0f);
        loss = __fadd_rn(loss, dv);
        out[O_LOSS] = loss;
        out[O_PERP] = perp;
    }
}

// ---------------- one-hot encodings (268 MB streaming write) ----------------
__global__ void enc_kernel(float* __restrict__ out) {
    float2* o2 = (float2*)(out + O_ENC);       // O_ENC*4 bytes is 8B-aligned
    size_t base = (size_t)blockIdx.x * 2048 + threadIdx.x;
    #pragma unroll
    for (int i = 0; i < 8; ++i) {
        size_t p = base + (size_t)i * 256;     // float2 index, < 33554432
        int linear = (int)(p << 1);
        int row = linear >> 10;
        int col = linear & 1023;
        int id  = g_idx[row];
        float2 v;
        v.x = (col     == id) ? 1.f : 0.f;
        v.y = (col + 1 == id) ? 1.f : 0.f;
        o2[p] = v;
    }
}

// ---------------- launch ----------------
extern "C" void kernel_launch(void* const* d_in, const int* in_sizes, int n_in,
                              void* d_out, int out_size) {
    const float* inputs = (const float*)d_in[0];
    const float* emb    = (const float*)d_in[1];
    if (n_in >= 2 && in_sizes[0] == KCODES * DIMD) {   // defensive: swapped order
        inputs = (const float*)d_in[1];
        emb    = (const float*)d_in[0];
    }
    float* out = (float*)d_out;

    prep_kernel<<<64, 1024>>>(emb);
    argmin_kernel<<<512, 256>>>(inputs, out);
    quant_kernel<<<QELEMS / 256, 256>>>(inputs, emb, out);
    finalize_kernel<<<1, 256>>>(out);
    enc_kernel<<<16384, 256>>>(out);
}

// round 2
// speedup vs baseline: 1.1264x; 1.1264x over previous
#include <cuda_runtime.h>
#include <cstdint>
#include <math.h>

// Problem constants
#define NROWS   65536          // 64*32*32 flattened vectors
#define DIMD    64
#define KCODES  1024
#define QELEMS  4194304        // 64*64*32*32

// Output layout (float32, concatenated in reference return order)
#define O_LOSS  0
#define O_QUANT 1
#define O_PERP  4194305
#define O_ENC   4194306
#define O_IDX   71303170

#define MARGIN  2.5e-3f

// ---------------- device scratch ----------------
__device__ float g_embT[DIMD * KCODES];   // emb transposed [d][k]
__device__ float g_B[KCODES];             // ||e_k||^2 (sequential add order)
__device__ int   g_idx[NROWS];
__device__ int   g_hist[KCODES];
__device__ float g_partial[16384];

// ---------------- helpers ----------------
__device__ __forceinline__ unsigned pack_bf16x2(float lo, float hi) {
    unsigned r;
    asm("cvt.rn.bf16x2.f32 %0, %1, %2;" : "=r"(r) : "f"(hi), "f"(lo));
    return r;
}
__device__ __forceinline__ void mma16816(float& c0, float& c1, float& c2, float& c3,
                                         unsigned a0, unsigned a1, unsigned a2, unsigned a3,
                                         unsigned b0, unsigned b1) {
    asm("mma.sync.aligned.m16n8k16.row.col.f32.bf16.bf16.f32 "
        "{%0,%1,%2,%3},{%4,%5,%6,%7},{%8,%9},{%0,%1,%2,%3};"
        : "+f"(c0), "+f"(c1), "+f"(c2), "+f"(c3)
        : "r"(a0), "r"(a1), "r"(a2), "r"(a3), "r"(b0), "r"(b1));
}

// ---------------- prep: transpose emb, codebook norms, zero hist ----------------
__global__ void prep_kernel(const float* __restrict__ emb) {
    int t = threadIdx.x;
    int d = blockIdx.x;               // 64 blocks x 1024 threads
    g_embT[d * KCODES + t] = emb[t * DIMD + d];
    if (blockIdx.x == 0) {
        const float* er = emb + t * DIMD;
        float s = 0.f;
        for (int dd = 0; dd < DIMD; ++dd) {
            float v = er[dd];
            s = __fadd_rn(s, __fmul_rn(v, v));
        }
        g_B[t] = s;
        g_hist[t] = 0;
    }
}

// ---------------- argmin: bf16 MMA filter + exact fp32 rescore ----------------
// Block = 64 rows x all 1024 codes. 128 threads = 4 warps, each warp owns 16 rows
// (m16 of the MMA). Phase 1: approx (B - 2*dot) via mma.sync bf16, tracking the
// min per 32-code subchunk per row. Phase 2: exact reference-rounded rescore of
// every subchunk within MARGIN of the row min; first-index tie rule.
__global__ void __launch_bounds__(128)
argmin_kernel(const float* __restrict__ inputs, float* __restrict__ out) {
    __shared__ float    Xs[64][65];       // exact fp32 X tile, padded
    __shared__ unsigned Ep[32][68];       // bf16x2 pairs: {e[2p][c], e[2p+1][c]}
    __shared__ float    Bs[64];           // ||e||^2 chunk
    __shared__ float    Cmin[32][64];     // subchunk approx min [sub][row]
    __shared__ float    rowA[64];         // exact ||x||^2 (sequential order)
    __shared__ float    rowlim[64];       // rowmin + margin

    const float INF = __int_as_float(0x7f800000);
    const int t = threadIdx.x;
    const int lane = t & 31;
    const int w = t >> 5;
    const int g = lane >> 2, tig = lane & 3;
    const int blk = blockIdx.x;                 // 1024 blocks of 64 rows
    const int b = blk >> 4, sp0 = (blk & 15) << 6;
    const float* xb = inputs + (size_t)b * 65536 + sp0;

    // Fill Xs[r][d] from NCHW (coalesced over spatial)
    #pragma unroll
    for (int it = 0; it < 8; ++it) {
        int idx = it * 128 + t;                 // 0..1023
        int d = idx >> 4, rq = idx & 15;
        float4 v = *(const float4*)(xb + d * 1024 + (rq << 2));
        Xs[4 * rq + 0][d] = v.x;
        Xs[4 * rq + 1][d] = v.y;
        Xs[4 * rq + 2][d] = v.z;
        Xs[4 * rq + 3][d] = v.w;
    }
    __syncthreads();

    // A-fragments in bf16 (rows R+g, R+8+g), held across whole phase 1
    const int R = w << 4;
    unsigned afr[16];
    {
        const float* r0 = Xs[R + g];
        const float* r1 = Xs[R + 8 + g];
        #pragma unroll
        for (int kk = 0; kk < 4; ++kk) {
            int c0 = 16 * kk + 2 * tig;
            afr[4 * kk + 0] = pack_bf16x2(r0[c0],     r0[c0 + 1]);
            afr[4 * kk + 1] = pack_bf16x2(r1[c0],     r1[c0 + 1]);
            afr[4 * kk + 2] = pack_bf16x2(r0[c0 + 8], r0[c0 + 9]);
            afr[4 * kk + 3] = pack_bf16x2(r1[c0 + 8], r1[c0 + 9]);
        }
    }
    // Exact ||x||^2 per row, reference order: sum of fl(x*x) with sequential add
    if (t < 64) {
        float a = 0.f;
        #pragma unroll 16
        for (int d = 0; d < DIMD; ++d) {
            float v = Xs[t][d];
            a = __fadd_rn(a, __fmul_rn(v, v));
        }
        rowA[t] = a;
    }

    // -------- Phase 1: approx distances + subchunk mins --------
    float sub_lo = INF, sub_hi = INF;
    for (int c = 0; c < 16; ++c) {              // 16 chunks of 64 codes
        __syncthreads();
        // stage E chunk as bf16 pairs along d
        #pragma unroll
        for (int it = 0; it < 4; ++it) {
            int idx = it * 128 + t;             // 0..511
            int p = idx >> 4, c4 = (idx & 15) << 2;
            const float* e0p = g_embT + (2 * p) * KCODES + (c << 6) + c4;
            const float* e1p = e0p + KCODES;
            float4 e0 = *(const float4*)e0p;
            float4 e1 = *(const float4*)e1p;
            Ep[p][c4 + 0] = pack_bf16x2(e0.x, e1.x);
            Ep[p][c4 + 1] = pack_bf16x2(e0.y, e1.y);
            Ep[p][c4 + 2] = pack_bf16x2(e0.z, e1.z);
            Ep[p][c4 + 3] = pack_bf16x2(e0.w, e1.w);
        }
        if (t < 64) Bs[t] = g_B[(c << 6) + t];
        __syncthreads();

        #pragma unroll
        for (int ct = 0; ct < 8; ++ct) {        // 8 col-tiles of 8 codes
            const int C = ct << 3;
            float c0 = 0.f, c1 = 0.f, c2 = 0.f, c3 = 0.f;
            #pragma unroll
            for (int kk = 0; kk < 4; ++kk) {
                unsigned b0 = Ep[8 * kk + tig][C + g];
                unsigned b1 = Ep[8 * kk + tig + 4][C + g];
                mma16816(c0, c1, c2, c3,
                         afr[4 * kk + 0], afr[4 * kk + 1],
                         afr[4 * kk + 2], afr[4 * kk + 3], b0, b1);
            }
            float B0 = Bs[C + 2 * tig], B1 = Bs[C + 2 * tig + 1];
            float v0 = fmaf(-2.f, c0, B0);
            float v1 = fmaf(-2.f, c1, B1);
            float v2 = fmaf(-2.f, c2, B0);
            float v3 = fmaf(-2.f, c3, B1);
            sub_lo = fminf(sub_lo, fminf(v0, v1));
            sub_hi = fminf(sub_hi, fminf(v2, v3));
            if ((ct & 3) == 3) {                // subchunk (32 codes) boundary
                sub_lo = fminf(sub_lo, __shfl_xor_sync(0xffffffffu, sub_lo, 1));
                sub_lo = fminf(sub_lo, __shfl_xor_sync(0xffffffffu, sub_lo, 2));
                sub_hi = fminf(sub_hi, __shfl_xor_sync(0xffffffffu, sub_hi, 1));
                sub_hi = fminf(sub_hi, __shfl_xor_sync(0xffffffffu, sub_hi, 2));
                int s = (c << 1) | (ct >> 2);
                if (tig == 0) {
                    Cmin[s][R + g]     = sub_lo;
                    Cmin[s][R + 8 + g] = sub_hi;
                }
                sub_lo = INF; sub_hi = INF;
            }
        }
    }
    __syncthreads();
    if (t < 64) {
        float m = INF;
        #pragma unroll
        for (int s = 0; s < 32; ++s) m = fminf(m, Cmin[s][t]);
        rowlim[t] = m + MARGIN;
    }
    __syncthreads();

    // -------- Phase 2: exact rescore of suspicious subchunks --------
    for (int rr = 0; rr < 16; ++rr) {
        const int row = (w << 4) + rr;
        const float lim = rowlim[row];
        const float A   = rowA[row];
        float bestv = INF;
        int   bestk = 0;
        for (int s = 0; s < 32; ++s) {
            if (Cmin[s][row] <= lim) {          // uniform per warp
                int k = (s << 5) + lane;
                const float* ep = g_embT + k;   // embT[d][k], stride KCODES
                float dot = 0.f;
                #pragma unroll 16
                for (int d = 0; d < DIMD; ++d)
                    dot = __fmaf_rn(Xs[row][d], ep[d << 10], dot);
                float dist = __fsub_rn(__fadd_rn(A, g_B[k]), __fmul_rn(2.f, dot));
                if (dist < bestv || (dist == bestv && k < bestk)) {
                    bestv = dist; bestk = k;
                }
            }
        }
        #pragma unroll
        for (int off = 16; off > 0; off >>= 1) {
            float v2 = __shfl_down_sync(0xffffffffu, bestv, off);
            int   k2 = __shfl_down_sync(0xffffffffu, bestk, off);
            if (v2 < bestv || (v2 == bestv && k2 < bestk)) { bestv = v2; bestk = k2; }
        }
        if (lane == 0) {
            int n = (blk << 6) + row;
            g_idx[n] = bestk;
            out[(size_t)O_IDX + n] = (float)bestk;
            atomicAdd(&g_hist[bestk], 1);
        }
    }
}

// ---------------- quantized gather (NCHW) + MSE partials ----------------
__global__ void quant_kernel(const float* __restrict__ inputs,
                             const float* __restrict__ emb,
                             float* __restrict__ out) {
    int e  = blockIdx.x * 256 + threadIdx.x;
    int sp = e & 1023;
    int d  = (e >> 10) & 63;
    int b  = e >> 16;
    int n  = (b << 10) + sp;
    int id = g_idx[n];
    float q = emb[id * DIMD + d];
    float x = inputs[e];
    out[O_QUANT + e] = q;
    float df = q - x;
    float s  = df * df;
    #pragma unroll
    for (int off = 16; off > 0; off >>= 1)
        s += __shfl_down_sync(0xffffffffu, s, off);
    __shared__ float ws[8];
    if ((threadIdx.x & 31) == 0) ws[threadIdx.x >> 5] = s;
    __syncthreads();
    if (threadIdx.x == 0) {
        float tot = 0.f;
        #pragma unroll
        for (int i = 0; i < 8; ++i) tot += ws[i];
        g_partial[blockIdx.x] = tot;
    }
}

// ---------------- scalars: loss + perplexity (parallelized) ----------------
__global__ void __launch_bounds__(1024)
finalize_kernel(float* __restrict__ out) {
    __shared__ double shd[1024];
    __shared__ float  shf[1024];
    int t = threadIdx.x;
    double s = 0.0;
    #pragma unroll
    for (int i = 0; i < 16; ++i) s += (double)g_partial[t + i * 1024];
    shd[t] = s;
    __syncthreads();
    #pragma unroll
    for (int off = 512; off > 0; off >>= 1) {
        if (t < off) shd[t] += shd[t + off];
        __syncthreads();
    }
    double S = shd[0];
    // entropy in fp32 (matches reference fp32 math)
    float p = (float)g_hist[t] * (1.0f / 65536.0f);
    shf[t] = p * logf(p + 1e-10f);
    __syncthreads();
    #pragma unroll
    for (int off = 512; off > 0; off >>= 1) {
        if (t < off) shf[t] += shf[t + off];
        __syncthreads();
    }
    if (t == 0) {
        float perp = expf(-shf[0]);
        float mse  = (float)(S * (1.0 / (double)QELEMS));
        float loss = __fadd_rn(mse, __fmul_rn(0.25f, mse));
        float dv   = __fdiv_rn(__fmul_rn(0.1f, __fsub_rn(1024.0f, perp)), 1024.0f);
        loss = __fadd_rn(loss, dv);
        out[O_LOSS] = loss;
        out[O_PERP] = perp;
    }
}

// ---------------- one-hot encodings (268 MB streaming write) ----------------
__global__ void enc_kernel(float* __restrict__ out) {
    float2* o2 = (float2*)(out + O_ENC);       // O_ENC is even -> 8B aligned
    size_t base = (size_t)blockIdx.x * 2048 + threadIdx.x;
    #pragma unroll
    for (int i = 0; i < 8; ++i) {
        size_t p = base + (size_t)i * 256;
        int linear = (int)(p << 1);
        int row = linear >> 10;
        int col = linear & 1023;
        int id  = g_idx[row];
        float2 v;
        v.x = (col     == id) ? 1.f : 0.f;
        v.y = (col + 1 == id) ? 1.f : 0.f;
        o2[p] = v;
    }
}

// ---------------- launch ----------------
extern "C" void kernel_launch(void* const* d_in, const int* in_sizes, int n_in,
                              void* d_out, int out_size) {
    const float* inputs = (const float*)d_in[0];
    const float* emb    = (const float*)d_in[1];
    if (n_in >= 2 && in_sizes[0] == KCODES * DIMD) {   // defensive: swapped order
        inputs = (const float*)d_in[1];
        emb    = (const float*)d_in[0];
    }
    float* out = (float*)d_out;

    prep_kernel<<<64, 1024>>>(emb);
    argmin_kernel<<<1024, 128>>>(inputs, out);
    quant_kernel<<<QELEMS / 256, 256>>>(inputs, emb, out);
    finalize_kernel<<<1, 1024>>>(out);
    enc_kernel<<<16384, 256>>>(out);
}

// round 4
// speedup vs baseline: 1.5467x; 1.3731x over previous
#include <cuda_runtime.h>
#include <cuda_bf16.h>
#include <cstdint>
#include <math.h>

// Problem constants
#define NROWS   65536
#define DIMD    64
#define KCODES  1024
#define QELEMS  4194304

// Output layout (float32, concatenated in reference return order)
#define O_LOSS  0
#define O_QUANT 1
#define O_PERP  4194305
#define O_ENC   4194306
#define O_IDX   71303170

#define MARGIN  1.5e-3f
#define WLCAP   1536

// ---------------- device scratch ----------------
__device__ float          g_embT[DIMD * KCODES];     // fp32 [d][k] for exact rescore
__device__ __nv_bfloat16  g_embB[KCODES * DIMD];     // bf16 [k][d] for MMA filter
__device__ float          g_B[KCODES];               // ||e_k||^2 exact order
__device__ int            g_idx[NROWS];
__device__ int            g_hist[KCODES];
__device__ float          g_partial[4096];

// ---------------- asm helpers ----------------
__device__ __forceinline__ unsigned pack_bf16x2(float lo, float hi) {
    unsigned r;
    asm("cvt.rn.bf16x2.f32 %0, %1, %2;" : "=r"(r) : "f"(hi), "f"(lo));
    return r;
}
__device__ __forceinline__ void mma16816(float& c0, float& c1, float& c2, float& c3,
                                         unsigned a0, unsigned a1, unsigned a2, unsigned a3,
                                         unsigned b0, unsigned b1) {
    asm("mma.sync.aligned.m16n8k16.row.col.f32.bf16.bf16.f32 "
        "{%0,%1,%2,%3},{%4,%5,%6,%7},{%8,%9},{%0,%1,%2,%3};"
        : "+f"(c0), "+f"(c1), "+f"(c2), "+f"(c3)
        : "r"(a0), "r"(a1), "r"(a2), "r"(a3), "r"(b0), "r"(b1));
}
__device__ __forceinline__ void ldsm4(unsigned& r0, unsigned& r1, unsigned& r2, unsigned& r3,
                                      const void* p) {
    unsigned a = (unsigned)__cvta_generic_to_shared(p);
    asm volatile("ldmatrix.sync.aligned.m8n8.x4.shared.b16 {%0,%1,%2,%3}, [%4];"
                 : "=r"(r0), "=r"(r1), "=r"(r2), "=r"(r3) : "r"(a));
}
__device__ __forceinline__ void cp16(void* sp, const void* gp) {
    unsigned a = (unsigned)__cvta_generic_to_shared(sp);
    asm volatile("cp.async.cg.shared.global [%0], [%1], 16;" :: "r"(a), "l"(gp));
}
#define CP_COMMIT() asm volatile("cp.async.commit_group;")
#define CP_WAIT0()  asm volatile("cp.async.wait_group 0;")

// ---------------- prep: transpose, bf16 pack, norms, hist ----------------
__global__ void prep_kernel(const float* __restrict__ emb) {
    int t = threadIdx.x;
    int b = blockIdx.x;                 // 64 blocks x 1024 threads
    // fp32 transpose: embT[d][k]
    g_embT[b * KCODES + t] = emb[t * DIMD + b];
    // bf16 pack, linear (coalesced)
    int i = b * 1024 + t;
    g_embB[i] = __float2bfloat16_rn(emb[i]);
    if (b == 0) {
        const float* er = emb + t * DIMD;
        float s = 0.f;
        for (int dd = 0; dd < DIMD; ++dd) {
            float v = er[dd];
            s = __fadd_rn(s, __fmul_rn(v, v));
        }
        g_B[t] = s;
        g_hist[t] = 0;
    }
}

// ---------------- argmin smem layout ----------------
struct ArgSmem {
    uint4 Es[2][512];                   // 16 KB : swizzled bf16 E-chunk, dbl-buffered
    float Xs[128][65];                  // 33.3 KB : fp32 X tile
    float Cmin[32][128];                // 16 KB : per-subchunk approx min
    float rowA[128];
    float rowlim[128];
    unsigned long long best[128];
    int   wl[WLCAP];
    int   nitems, wtake;
};
#define ARG_SMEM_BYTES sizeof(ArgSmem)

__device__ __forceinline__ void stageE(ArgSmem* sm, int c, int t) {
    const char* gb = (const char*)g_embB + (size_t)(c << 6) * 128;
    #pragma unroll
    for (int it = 0; it < 2; ++it) {
        int id = it * 256 + t;          // 0..511 cells
        int code = id >> 3, h = id & 7;
        int cell = (code << 3) | (h ^ (code & 7));
        cp16(&sm->Es[c & 1][cell], gb + code * 128 + h * 16);
    }
}

// ---------------- argmin: MMA filter + exact rescore ----------------
__global__ void __launch_bounds__(256)
argmin_kernel(const float* __restrict__ inputs, float* __restrict__ out) {
    extern __shared__ char raw[];
    ArgSmem* sm = (ArgSmem*)raw;

    const float INF = __int_as_float(0x7f800000);
    const int t = threadIdx.x;
    const int lane = t & 31;
    const int w = t >> 5;               // 8 warps
    const int g = lane >> 2, tig = lane & 3;
    const int blk = blockIdx.x;         // 512 blocks of 128 rows
    const int b = blk >> 3, sp0 = (blk & 7) << 7;
    const float* xb = inputs + (size_t)b * 65536 + sp0;

    if (t < 128) sm->best[t] = 0xFFFFFFFFFFFFFFFFULL;
    if (t == 0) { sm->nitems = 0; sm->wtake = 0; }

    // X tile: Xs[r][d]
    #pragma unroll
    for (int it = 0; it < 8; ++it) {
        int id4 = it * 256 + t;         // 0..2047
        int d = id4 >> 5, rq = id4 & 31;
        float4 v = *(const float4*)(xb + d * 1024 + (rq << 2));
        sm->Xs[4 * rq + 0][d] = v.x;
        sm->Xs[4 * rq + 1][d] = v.y;
        sm->Xs[4 * rq + 2][d] = v.z;
        sm->Xs[4 * rq + 3][d] = v.w;
    }
    stageE(sm, 0, t);                   // prefetch chunk 0
    CP_COMMIT();
    __syncthreads();

    // A-fragments (rows R+g, R+8+g) held in regs for whole phase 1
    const int R = w << 4;
    unsigned afr[16];
    {
        const float* r0 = sm->Xs[R + g];
        const float* r1 = sm->Xs[R + 8 + g];
        #pragma unroll
        for (int kk = 0; kk < 4; ++kk) {
            int c0 = 16 * kk + 2 * tig;
            afr[4 * kk + 0] = pack_bf16x2(r0[c0],     r0[c0 + 1]);
            afr[4 * kk + 1] = pack_bf16x2(r1[c0],     r1[c0 + 1]);
            afr[4 * kk + 2] = pack_bf16x2(r0[c0 + 8], r0[c0 + 9]);
            afr[4 * kk + 3] = pack_bf16x2(r1[c0 + 8], r1[c0 + 9]);
        }
    }
    // exact ||x||^2, reference order
    if (t < 128) {
        float a = 0.f;
        #pragma unroll 16
        for (int d = 0; d < DIMD; ++d) {
            float v = sm->Xs[t][d];
            a = __fadd_rn(a, __fmul_rn(v, v));
        }
        sm->rowA[t] = a;
    }

    // -------- Phase 1 --------
    float sub_lo = INF, sub_hi = INF;
    for (int c = 0; c < 16; ++c) {
        CP_WAIT0();
        __syncthreads();
        if (c + 1 < 16) { stageE(sm, c + 1, t); CP_COMMIT(); }
        const uint4* Eb = sm->Es[c & 1];
        const int kc = c << 6;
        #pragma unroll
        for (int ct = 0; ct < 8; ++ct) {
            const int C = ct << 3;
            float c0 = 0.f, c1 = 0.f, c2 = 0.f, c3 = 0.f;
            #pragma unroll
            for (int kk2 = 0; kk2 < 2; ++kk2) {
                int code = C + (lane & 7);
                int h = (kk2 << 2) + (lane >> 3);
                unsigned q0, q1, q2, q3;
                ldsm4(q0, q1, q2, q3, Eb + ((code << 3) | (h ^ (code & 7))));
                mma16816(c0, c1, c2, c3, afr[8 * kk2 + 0], afr[8 * kk2 + 1],
                         afr[8 * kk2 + 2], afr[8 * kk2 + 3], q0, q1);
                mma16816(c0, c1, c2, c3, afr[8 * kk2 + 4], afr[8 * kk2 + 5],
                         afr[8 * kk2 + 6], afr[8 * kk2 + 7], q2, q3);
            }
            float B0 = __ldg(&g_B[kc + C + 2 * tig]);
            float B1 = __ldg(&g_B[kc + C + 2 * tig + 1]);
            float v0 = fmaf(-2.f, c0, B0);
            float v1 = fmaf(-2.f, c1, B1);
            float v2 = fmaf(-2.f, c2, B0);
            float v3 = fmaf(-2.f, c3, B1);
            sub_lo = fminf(sub_lo, fminf(v0, v1));
            sub_hi = fminf(sub_hi, fminf(v2, v3));
            if ((ct & 3) == 3) {
                sub_lo = fminf(sub_lo, __shfl_xor_sync(0xffffffffu, sub_lo, 1));
                sub_lo = fminf(sub_lo, __shfl_xor_sync(0xffffffffu, sub_lo, 2));
                sub_hi = fminf(sub_hi, __shfl_xor_sync(0xffffffffu, sub_hi, 1));
                sub_hi = fminf(sub_hi, __shfl_xor_sync(0xffffffffu, sub_hi, 2));
                int s = (c << 1) | (ct >> 2);
                if (tig == 0) {
                    sm->Cmin[s][R + g]     = sub_lo;
                    sm->Cmin[s][R + 8 + g] = sub_hi;
                }
                sub_lo = INF; sub_hi = INF;
            }
        }
    }
    __syncthreads();

    // -------- Phase 2: worklist + exact rescore --------
    if (t < 128) {
        float m = INF;
        #pragma unroll
        for (int s = 0; s < 32; ++s) m = fminf(m, sm->Cmin[s][t]);
        sm->rowlim[t] = m + MARGIN;
    }
    __syncthreads();
    if (t < 128) {
        float lim = sm->rowlim[t];
        #pragma unroll 4
        for (int s = 0; s < 32; ++s) {
            if (sm->Cmin[s][t] <= lim) {
                int pos = atomicAdd(&sm->nitems, 1);
                if (pos < WLCAP) sm->wl[pos] = (t << 5) | s;
            }
        }
    }
    __syncthreads();
    const int NI = min(sm->nitems, WLCAP);
    while (true) {
        int i = 0;
        if (lane == 0) i = atomicAdd(&sm->wtake, 1);
        i = __shfl_sync(0xffffffffu, i, 0);
        if (i >= NI) break;
        int item = sm->wl[i];
        int row = item >> 5, s = item & 31;
        int k = (s << 5) + lane;
        const float* ep = g_embT + k;
        float dot = 0.f;
        #pragma unroll 16
        for (int d = 0; d < DIMD; ++d)
            dot = __fmaf_rn(sm->Xs[row][d], ep[d << 10], dot);
        float dist = __fsub_rn(__fadd_rn(sm->rowA[row], g_B[k]), __fmul_rn(2.f, dot));
        unsigned long long pk = ((unsigned long long)__float_as_uint(dist) << 32) | (unsigned)k;
        #pragma unroll
        for (int off = 16; off > 0; off >>= 1) {
            unsigned long long o = __shfl_down_sync(0xffffffffu, pk, off);
            if (o < pk) pk = o;
        }
        if (lane == 0) atomicMin(&sm->best[row], pk);
    }
    __syncthreads();
    if (t < 128) {
        int k = (int)(unsigned)(sm->best[t] & 0xffffffffULL);
        int n = (blk << 7) + t;
        g_idx[n] = k;
        out[(size_t)O_IDX + n] = (float)k;
        atomicAdd(&g_hist[k], 1);
    }
}

// ---------------- quantized gather + MSE partials ----------------
__global__ void __launch_bounds__(1024)
quant_kernel(const float* __restrict__ inputs, const float* __restrict__ emb,
             float* __restrict__ out) {
    int e  = blockIdx.x * 1024 + threadIdx.x;
    int sp = e & 1023;
    int d  = (e >> 10) & 63;
    int b  = e >> 16;
    int id = g_idx[(b << 10) + sp];
    float q = emb[id * DIMD + d];
    float x = inputs[e];
    out[O_QUANT + e] = q;
    float df = q - x;
    float s  = df * df;
    #pragma unroll
    for (int off = 16; off > 0; off >>= 1)
        s += __shfl_down_sync(0xffffffffu, s, off);
    __shared__ float ws[32];
    if ((threadIdx.x & 31) == 0) ws[threadIdx.x >> 5] = s;
    __syncthreads();
    if (threadIdx.x < 32) {
        float v = ws[threadIdx.x];
        #pragma unroll
        for (int off = 16; off > 0; off >>= 1)
            v += __shfl_down_sync(0xffffffffu, v, off);
        if (threadIdx.x == 0) g_partial[blockIdx.x] = v;
    }
}

// ---------------- scalars: loss + perplexity ----------------
__global__ void __launch_bounds__(1024)
finalize_kernel(float* __restrict__ out) {
    __shared__ float ws[32];
    int t = threadIdx.x, lane = t & 31, w = t >> 5;
    float s = g_partial[t] + g_partial[t + 1024] + g_partial[t + 2048] + g_partial[t + 3072];
    #pragma unroll
    for (int off = 16; off > 0; off >>= 1) s += __shfl_down_sync(0xffffffffu, s, off);
    if (lane == 0) ws[w] = s;
    __syncthreads();
    float S = 0.f;
    if (t < 32) {
        float v = ws[t];
        #pragma unroll
        for (int off = 16; off > 0; off >>= 1) v += __shfl_down_sync(0xffffffffu, v, off);
        if (t == 0) ws[0] = v;
    }
    __syncthreads();
    S = ws[0];
    __syncthreads();
    float p = (float)g_hist[t] * (1.0f / 65536.0f);
    float h = p * logf(p + 1e-10f);
    #pragma unroll
    for (int off = 16; off > 0; off >>= 1) h += __shfl_down_sync(0xffffffffu, h, off);
    if (lane == 0) ws[w] = h;
    __syncthreads();
    if (t < 32) {
        float v = ws[t];
        #pragma unroll
        for (int off = 16; off > 0; off >>= 1) v += __shfl_down_sync(0xffffffffu, v, off);
        if (t == 0) {
            float perp = expf(-v);
            float mse  = S * (1.0f / (float)QELEMS);
            float loss = __fadd_rn(mse, __fmul_rn(0.25f, mse));
            float dv   = __fdiv_rn(__fmul_rn(0.1f, __fsub_rn(1024.0f, perp)), 1024.0f);
            out[O_LOSS] = __fadd_rn(loss, dv);
            out[O_PERP] = perp;
        }
    }
}

// ---------------- one-hot encodings (268 MB streaming write) ----------------
__global__ void enc_kernel(float* __restrict__ out) {
    float2* o2 = (float2*)(out + O_ENC);
    size_t base = (size_t)blockIdx.x * 2048 + threadIdx.x;
    #pragma unroll
    for (int i = 0; i < 8; ++i) {
        size_t p = base + (size_t)i * 256;
        int linear = (int)(p << 1);
        int row = linear >> 10;
        int col = linear & 1023;
        int id  = g_idx[row];
        float2 v;
        v.x = (col     == id) ? 1.f : 0.f;
        v.y = (col + 1 == id) ? 1.f : 0.f;
        o2[p] = v;
    }
}

// ---------------- launch ----------------
extern "C" void kernel_launch(void* const* d_in, const int* in_sizes, int n_in,
                              void* d_out, int out_size) {
    const float* inputs = (const float*)d_in[0];
    const float* emb    = (const float*)d_in[1];
    if (n_in >= 2 && in_sizes[0] == KCODES * DIMD) {
        inputs = (const float*)d_in[1];
        emb    = (const float*)d_in[0];
    }
    float* out = (float*)d_out;

    cudaFuncSetAttribute(argmin_kernel, cudaFuncAttributeMaxDynamicSharedMemorySize,
                         (int)ARG_SMEM_BYTES);

    prep_kernel<<<64, 1024>>>(emb);
    argmin_kernel<<<512, 256, ARG_SMEM_BYTES>>>(inputs, out);
    quant_kernel<<<QELEMS / 1024, 1024>>>(inputs, emb, out);
    finalize_kernel<<<1, 1024>>>(out);
    enc_kernel<<<16384, 256>>>(out);
}